// round 8
// baseline (speedup 1.0000x reference)
#include <cuda_runtime.h>
#include <cstdint>

// Problem constants
#define NN     8192
#define HH     1024
#define B0     64
#define FF     2048
#define OO     2048
#define NBLK   6
#define XW     (HH + B0 + FF)   // 3136

// ---------------- scratch buffers (device globals; no allocation) ----------------
__device__ float g_q    [NN * FF];
__device__ float g_sumq [NN * FF];
__device__ float g_resS [NN * FF];
__device__ float g_Aq   [NN * FF];
__device__ float g_sumh [NN * HH];
__device__ float g_resqh[NN * HH];
__device__ float g_Dh   [NN * HH];
__device__ float g_h    [NN * HH];

// ---------------- elementwise: q = pi/4 * d^2, d = x[:, 1088:3136] ----------------
__global__ void square_k(const float* __restrict__ x, float* __restrict__ q) {
    int i = blockIdx.x * blockDim.x + threadIdx.x;   // over NN * FF / 4
    // FF/4 = 512 float4 per row
    int row = i >> 9;
    int col = i & 511;
    const float c = 0.78539816339744830962f; // pi/4
    float4 v = *(const float4*)(x + (size_t)row * XW + (HH + B0) + col * 4);
    float4 o;
    o.x = c * v.x * v.x;
    o.y = c * v.y * v.y;
    o.z = c * v.z * v.z;
    o.w = c * v.w * v.w;
    *(float4*)(q + ((size_t)i << 2)) = o;
}

// ---------------- generic fused GEMM: C = epi( fuseA(A...) @ B^T + bias ) ----------------
// AMODE: 0: a = A0
//        1: a = A0 * A1
//        2: a = A0 * (A1 + A2)
//        3: a = (A0 + A1 + A2) * A3
// EMODE: 0: C = v + bias
//        1: C = relu(v + bias)
//        2: C = C + v + bias                (accumulate)
//        3: z = leaky(v + bias, alpha); C = qin - z
// A0 has row stride lda0; A1..A3 are dense with row stride K.
#define TM 128
#define TN 128
#define TK 16

template<int AMODE, int EMODE>
__global__ __launch_bounds__(256, 2) void gemm_k(
    const float* __restrict__ A0, int lda0,
    const float* __restrict__ A1,
    const float* __restrict__ A2,
    const float* __restrict__ A3,
    const float* __restrict__ B,     // [Nn, K] row-major
    const float* __restrict__ bias,  // [Nn]
    float* __restrict__ C,           // [M, Nn]
    const float* __restrict__ qin,   // EMODE 3
    const float* __restrict__ alpha_ptr, int alpha_idx,
    int M, int Nn, int K)
{
    __shared__ float As[TK][TM];
    __shared__ float Bs[TK][TN];

    const int tid = threadIdx.x;
    const int tx = tid & 15;     // 0..15  (cols)
    const int ty = tid >> 4;     // 0..15  (rows)
    const int bm = blockIdx.y * TM;
    const int bn = blockIdx.x * TN;

    const int arow = tid >> 2;        // 0..63
    const int acol = (tid & 3) * 4;   // 0,4,8,12

    float acc[8][8];
#pragma unroll
    for (int i = 0; i < 8; i++)
#pragma unroll
        for (int j = 0; j < 8; j++) acc[i][j] = 0.f;

    for (int k0 = 0; k0 < K; k0 += TK) {
        // ---- load A tile (with fusion) ----
#pragma unroll
        for (int r = 0; r < 2; r++) {
            int m = arow + r * 64;
            size_t gm = (size_t)(bm + m);
            float4 v = *(const float4*)(A0 + gm * (size_t)lda0 + k0 + acol);
            if (AMODE == 1) {
                float4 w = *(const float4*)(A1 + gm * (size_t)K + k0 + acol);
                v.x *= w.x; v.y *= w.y; v.z *= w.z; v.w *= w.w;
            } else if (AMODE == 2) {
                float4 w1 = *(const float4*)(A1 + gm * (size_t)K + k0 + acol);
                float4 w2 = *(const float4*)(A2 + gm * (size_t)K + k0 + acol);
                v.x *= (w1.x + w2.x); v.y *= (w1.y + w2.y);
                v.z *= (w1.z + w2.z); v.w *= (w1.w + w2.w);
            } else if (AMODE == 3) {
                float4 w1 = *(const float4*)(A1 + gm * (size_t)K + k0 + acol);
                float4 w2 = *(const float4*)(A2 + gm * (size_t)K + k0 + acol);
                float4 w3 = *(const float4*)(A3 + gm * (size_t)K + k0 + acol);
                v.x = (v.x + w1.x + w2.x) * w3.x;
                v.y = (v.y + w1.y + w2.y) * w3.y;
                v.z = (v.z + w1.z + w2.z) * w3.z;
                v.w = (v.w + w1.w + w2.w) * w3.w;
            }
            As[acol + 0][m] = v.x;
            As[acol + 1][m] = v.y;
            As[acol + 2][m] = v.z;
            As[acol + 3][m] = v.w;
        }
        // ---- load B tile ----
#pragma unroll
        for (int r = 0; r < 2; r++) {
            int n = arow + r * 64;
            float4 v = *(const float4*)(B + (size_t)(bn + n) * K + k0 + acol);
            Bs[acol + 0][n] = v.x;
            Bs[acol + 1][n] = v.y;
            Bs[acol + 2][n] = v.z;
            Bs[acol + 3][n] = v.w;
        }
        __syncthreads();

#pragma unroll
        for (int kk = 0; kk < TK; kk++) {
            float af[8], bf[8];
#pragma unroll
            for (int i = 0; i < 8; i++) af[i] = As[kk][ty * 8 + i];
#pragma unroll
            for (int j = 0; j < 8; j++) bf[j] = Bs[kk][tx * 8 + j];
#pragma unroll
            for (int i = 0; i < 8; i++)
#pragma unroll
                for (int j = 0; j < 8; j++) acc[i][j] += af[i] * bf[j];
        }
        __syncthreads();
    }

    float alpha = 0.f;
    if (EMODE == 3) alpha = alpha_ptr[alpha_idx];

#pragma unroll
    for (int i = 0; i < 8; i++) {
        size_t gm = (size_t)(bm + ty * 8 + i);
#pragma unroll
        for (int j = 0; j < 8; j++) {
            int gn = bn + tx * 8 + j;
            float v = acc[i][j] + bias[gn];
            size_t idx = gm * (size_t)Nn + gn;
            if (EMODE == 0) {
                C[idx] = v;
            } else if (EMODE == 1) {
                C[idx] = fmaxf(v, 0.f);
            } else if (EMODE == 2) {
                C[idx] = C[idx] + v;
            } else { // EMODE == 3
                float z = (v >= 0.f) ? v : alpha * v;
                C[idx] = qin[idx] - z;
            }
        }
    }
}

// ---------------- host launch ----------------
static inline dim3 gemm_grid(int M, int Nn) { return dim3(Nn / TN, M / TM); }

extern "C" void kernel_launch(void* const* d_in, const int* in_sizes, int n_in,
                              void* d_out, int out_size)
{
    const float* x      = (const float*)d_in[0];
    const float* W_h0q  = (const float*)d_in[1];
    const float* b_h0q  = (const float*)d_in[2];
    const float* W_sq   = (const float*)d_in[3];
    const float* b_sq   = (const float*)d_in[4];
    const float* W_h0h  = (const float*)d_in[5];
    const float* b_h0h  = (const float*)d_in[6];
    const float* W_S    = (const float*)d_in[7];
    const float* b_S    = (const float*)d_in[8];
    const float* W_q0h  = (const float*)d_in[9];
    const float* b_q0h  = (const float*)d_in[10];
    const float* Wb_Aq  = (const float*)d_in[11];
    const float* bb_Aq  = (const float*)d_in[12];
    const float* Wb_Dh  = (const float*)d_in[13];
    const float* bb_Dh  = (const float*)d_in[14];
    const float* Wb_fh  = (const float*)d_in[15];
    const float* bb_fh  = (const float*)d_in[16];
    const float* Wb_hf  = (const float*)d_in[17];
    const float* bb_hf  = (const float*)d_in[18];
    const float* a_hf   = (const float*)d_in[19];
    const float* Wb_resq= (const float*)d_in[20];
    const float* bb_resq= (const float*)d_in[21];
    const float* W_out  = (const float*)d_in[22];
    const float* b_out  = (const float*)d_in[23];
    float* out = (float*)d_out;

    float *q, *sumq, *sumh, *resS, *resqh, *Aq, *Dh, *h;
    cudaGetSymbolAddress((void**)&q,     g_q);
    cudaGetSymbolAddress((void**)&sumq,  g_sumq);
    cudaGetSymbolAddress((void**)&sumh,  g_sumh);
    cudaGetSymbolAddress((void**)&resS,  g_resS);
    cudaGetSymbolAddress((void**)&resqh, g_resqh);
    cudaGetSymbolAddress((void**)&Aq,    g_Aq);
    cudaGetSymbolAddress((void**)&Dh,    g_Dh);
    cudaGetSymbolAddress((void**)&h,     g_h);

    const int threads = 256;

    // q = pi/4 * d^2
    square_k<<<(NN * FF / 4) / threads, threads>>>(x, q);

    // sum_q_const = s @ W_sq^T + b_sq
    gemm_k<0, 0><<<gemm_grid(NN, FF), threads>>>(
        x, XW, nullptr, nullptr, nullptr, W_sq, b_sq, sumq,
        nullptr, nullptr, 0, NN, FF, HH);

    // sum_q_const += h0 @ W_h0q^T + b_h0q
    gemm_k<0, 2><<<gemm_grid(NN, FF), threads>>>(
        x + HH, XW, nullptr, nullptr, nullptr, W_h0q, b_h0q, sumq,
        nullptr, nullptr, 0, NN, FF, B0);

    // sum_h_const = h0 @ W_h0h^T + b_h0h
    gemm_k<0, 0><<<gemm_grid(NN, HH), threads>>>(
        x + HH, XW, nullptr, nullptr, nullptr, W_h0h, b_h0h, sumh,
        nullptr, nullptr, 0, NN, HH, B0);

    // res_S_q = relu(d @ W_S^T + b_S)
    gemm_k<0, 1><<<gemm_grid(NN, FF), threads>>>(
        x + HH + B0, XW, nullptr, nullptr, nullptr, W_S, b_S, resS,
        nullptr, nullptr, 0, NN, FF, FF);

    // res_q_h = q @ W_q0h^T + b_q0h
    gemm_k<0, 0><<<gemm_grid(NN, HH), threads>>>(
        q, FF, nullptr, nullptr, nullptr, W_q0h, b_q0h, resqh,
        nullptr, nullptr, 0, NN, HH, FF);

    for (int i = 0; i < NBLK; i++) {
        const float* W_Aq_i   = Wb_Aq   + (size_t)i * FF * FF;
        const float* b_Aq_i   = bb_Aq   + (size_t)i * FF;
        const float* W_Dh_i   = Wb_Dh   + (size_t)i * HH * FF;
        const float* b_Dh_i   = bb_Dh   + (size_t)i * HH;
        const float* W_fh_i   = Wb_fh   + (size_t)i * HH * FF;
        const float* b_fh_i   = bb_fh   + (size_t)i * HH;
        const float* W_hf_i   = Wb_hf   + (size_t)i * FF * HH;
        const float* b_hf_i   = bb_hf   + (size_t)i * FF;
        const float* W_resq_i = Wb_resq + (size_t)i * HH * FF;
        const float* b_resq_i = bb_resq + (size_t)i * HH;

        // A_q = (q * res_S_q) @ W_Aq^T + b_Aq
        gemm_k<1, 0><<<gemm_grid(NN, FF), threads>>>(
            q, FF, resS, nullptr, nullptr, W_Aq_i, b_Aq_i, Aq,
            nullptr, nullptr, 0, NN, FF, FF);

        // D_h = relu(A_q @ W_Dh^T + b_Dh)
        gemm_k<0, 1><<<gemm_grid(NN, HH), threads>>>(
            Aq, FF, nullptr, nullptr, nullptr, W_Dh_i, b_Dh_i, Dh,
            nullptr, nullptr, 0, NN, HH, FF);

        // h = relu( (A_q * (q + sum_q_const)) @ W_fh^T + b_fh )
        gemm_k<2, 1><<<gemm_grid(NN, HH), threads>>>(
            Aq, FF, q, sumq, nullptr, W_fh_i, b_fh_i, h,
            nullptr, nullptr, 0, NN, HH, FF);

        // z = ((h + sum_h_const + res_q_h) * D_h) @ W_hf^T + b_hf
        // z = leaky(z, a[i]); q = q - z
        gemm_k<3, 3><<<gemm_grid(NN, FF), threads>>>(
            h, HH, sumh, resqh, Dh, W_hf_i, b_hf_i, q,
            q, a_hf, i, NN, FF, HH);

        // res_q_h = relu(q @ W_resq^T + b_resq)
        gemm_k<0, 1><<<gemm_grid(NN, HH), threads>>>(
            q, FF, nullptr, nullptr, nullptr, W_resq_i, b_resq_i, resqh,
            nullptr, nullptr, 0, NN, HH, FF);
    }

    // out = q @ W_out^T + b_out
    gemm_k<0, 0><<<gemm_grid(NN, OO), threads>>>(
        q, FF, nullptr, nullptr, nullptr, W_out, b_out, out,
        nullptr, nullptr, 0, NN, OO, FF);
}

// round 15
// speedup vs baseline: 2.1210x; 2.1210x over previous
#include <cuda_runtime.h>
#include <cuda_bf16.h>
#include <cstdint>

// ---------------- problem constants ----------------
#define NN     8192
#define HH     1024
#define B0K    64
#define FF     2048
#define OO     2048
#define NBLK   6
#define XW     3136         // HH + B0K + FF

// ---------------- activation scratch (fp32) ----------------
__device__ float g_q    [NN * FF];
__device__ float g_sumq [NN * FF];
__device__ float g_resS [NN * FF];
__device__ float g_Aq   [NN * FF];
__device__ float g_sumh [NN * HH];
__device__ float g_resqh[NN * HH];
__device__ float g_Dh   [NN * HH];
__device__ float g_h    [NN * HH];

// ---------------- A-operand bf16 hi/lo (per-GEMM, reused) ----------------
__device__ __nv_bfloat16 g_Ahi[NN * FF];
__device__ __nv_bfloat16 g_Alo[NN * FF];

// ---------------- weight hi/lo bf16 storage (concatenated) ----------------
// SQC = [W_sq | W_h0q] rows of 1088
#define O_SQC  0ull           // 2048 x 1088
#define O_H0H  2228224ull     // 1024 x 64
#define O_WS   2293760ull     // 2048 x 2048
#define O_Q0H  6488064ull     // 1024 x 2048
#define O_AQ   8585216ull     // 6 x 2048 x 2048
#define O_DH   33751040ull    // 6 x 1024 x 2048
#define O_FH   46333952ull    // 6 x 1024 x 2048
#define O_HF   58916864ull    // 6 x 2048 x 1024
#define O_RESQ 71499776ull    // 6 x 1024 x 2048
#define O_OUT  84082688ull    // 2048 x 2048

__device__ __nv_bfloat16 g_Whi[88276992];
__device__ __nv_bfloat16 g_Wlo[88276992];
__device__ float g_bsum[FF];

// ---------------- small helpers ----------------
__device__ __forceinline__ uint32_t smem_u32(const void* p) {
    uint32_t a;
    asm("{ .reg .u64 t; cvta.to.shared.u64 t, %1; cvt.u32.u64 %0, t; }" : "=r"(a) : "l"(p));
    return a;
}

__device__ __forceinline__ void ldsm4(uint32_t* r, uint32_t a) {
    asm volatile("ldmatrix.sync.aligned.m8n8.x4.shared.b16 {%0,%1,%2,%3}, [%4];\n"
                 : "=r"(r[0]), "=r"(r[1]), "=r"(r[2]), "=r"(r[3]) : "r"(a));
}

__device__ __forceinline__ void mma16816(float* d, const uint32_t* a, const uint32_t* b) {
    asm volatile(
        "mma.sync.aligned.m16n8k16.row.col.f32.bf16.bf16.f32 "
        "{%0,%1,%2,%3}, {%4,%5,%6,%7}, {%8,%9}, {%0,%1,%2,%3};\n"
        : "+f"(d[0]), "+f"(d[1]), "+f"(d[2]), "+f"(d[3])
        : "r"(a[0]), "r"(a[1]), "r"(a[2]), "r"(a[3]),
          "r"(b[0]), "r"(b[1]));
}

#define CPA(dst, src) \
    asm volatile("cp.async.cg.shared.global [%0], [%1], 16;\n" \
                 :: "r"(dst), "l"(__cvta_generic_to_global((const void*)(src))) : "memory")
#define CP_COMMIT() asm volatile("cp.async.commit_group;\n" ::: "memory")
#define CP_WAIT(n)  asm volatile("cp.async.wait_group %0;\n" :: "n"(n) : "memory")

// ---------------- elementwise: q = pi/4 * d^2 ----------------
__global__ void square_k(const float* __restrict__ x, float* __restrict__ q) {
    int i = blockIdx.x * blockDim.x + threadIdx.x;
    int row = i >> 9;
    int col = i & 511;
    const float c = 0.78539816339744830962f;
    float4 v = *(const float4*)(x + (size_t)row * XW + (HH + B0K) + col * 4);
    float4 o;
    o.x = c * v.x * v.x; o.y = c * v.y * v.y;
    o.z = c * v.z * v.z; o.w = c * v.w * v.w;
    *(float4*)(q + ((size_t)i << 2)) = o;
}

// ---------------- weight split fp32 -> bf16 hi/lo (strided dst) ----------------
__global__ void wsplit_k(const float* __restrict__ src,
                         __nv_bfloat16* __restrict__ hi,
                         __nv_bfloat16* __restrict__ lo,
                         int cols, int dstride, int n) {
    int i = blockIdx.x * blockDim.x + threadIdx.x;
    if (i >= n) return;
    int r = i / cols, c = i - r * cols;
    float v = src[i];
    __nv_bfloat16 h = __float2bfloat16(v);
    size_t o = (size_t)r * dstride + c;
    hi[o] = h;
    lo[o] = __float2bfloat16(v - __bfloat162float(h));
}

__global__ void badd_k(const float* __restrict__ a, const float* __restrict__ b,
                       float* __restrict__ o, int n) {
    int i = blockIdx.x * blockDim.x + threadIdx.x;
    if (i < n) o[i] = a[i] + b[i];
}

// ---------------- A fuse + split ----------------
// AMODE: 0: a=A0   1: a=A0*A1   2: a=A0*(A1+A2)   3: a=(A0+A1+A2)*A3
template<int AMODE>
__global__ void asplit_k(const float* __restrict__ A0, int lda0,
                         const float* __restrict__ A1,
                         const float* __restrict__ A2,
                         const float* __restrict__ A3,
                         __nv_bfloat16* __restrict__ hi,
                         __nv_bfloat16* __restrict__ lo,
                         int cols4, int K) {
    int i = blockIdx.x * blockDim.x + threadIdx.x;   // over M*K/4
    int r = i / cols4, c4 = i - r * cols4;
    int c = c4 * 4;
    size_t gr = (size_t)r;
    float4 v = *(const float4*)(A0 + gr * lda0 + c);
    if (AMODE == 1) {
        float4 w = *(const float4*)(A1 + gr * K + c);
        v.x *= w.x; v.y *= w.y; v.z *= w.z; v.w *= w.w;
    } else if (AMODE == 2) {
        float4 w1 = *(const float4*)(A1 + gr * K + c);
        float4 w2 = *(const float4*)(A2 + gr * K + c);
        v.x *= (w1.x + w2.x); v.y *= (w1.y + w2.y);
        v.z *= (w1.z + w2.z); v.w *= (w1.w + w2.w);
    } else if (AMODE == 3) {
        float4 w1 = *(const float4*)(A1 + gr * K + c);
        float4 w2 = *(const float4*)(A2 + gr * K + c);
        float4 w3 = *(const float4*)(A3 + gr * K + c);
        v.x = (v.x + w1.x + w2.x) * w3.x;
        v.y = (v.y + w1.y + w2.y) * w3.y;
        v.z = (v.z + w1.z + w2.z) * w3.z;
        v.w = (v.w + w1.w + w2.w) * w3.w;
    }
    __nv_bfloat162 h01 = __floats2bfloat162_rn(v.x, v.y);
    __nv_bfloat162 h23 = __floats2bfloat162_rn(v.z, v.w);
    float2 f01 = __bfloat1622float2(h01);
    float2 f23 = __bfloat1622float2(h23);
    __nv_bfloat162 l01 = __floats2bfloat162_rn(v.x - f01.x, v.y - f01.y);
    __nv_bfloat162 l23 = __floats2bfloat162_rn(v.z - f23.x, v.w - f23.y);
    size_t o = gr * K + c;
    uint2 hv, lv;
    hv.x = *reinterpret_cast<uint32_t*>(&h01);
    hv.y = *reinterpret_cast<uint32_t*>(&h23);
    lv.x = *reinterpret_cast<uint32_t*>(&l01);
    lv.y = *reinterpret_cast<uint32_t*>(&l23);
    *(uint2*)(hi + o) = hv;
    *(uint2*)(lo + o) = lv;
}

// ---------------- bf16 HMMA GEMM ----------------
// C[M,Nn] = epi( A @ B^T + bias ), A given as hi/lo bf16 [M,K], B as hi/lo [Nn,K].
// 3 passes: Ahi*Bhi + Ahi*Blo + Alo*Bhi, fp32 accumulate.
// EMODE: 0: v   1: relu(v)   3: z=leaky(v,alpha); C=qin-z
// Tile 128x128xBK=32; 8 warps, warp tile 64x32; 4-stage cp.async pipeline.
// SMEM rows padded to 40 bf16 (80B): 80 % 16 == 0 (cp.async OK), banks r*20%32 distinct (ldmatrix conflict-free).

#define SSN    4
#define TIL_B  10240           // 128 rows * 80B
#define STG_B  (4 * TIL_B)     // Ahi, Alo, Bhi, Blo
#define GSMEM  (SSN * STG_B)   // 163840

template<int EMODE>
__global__ __launch_bounds__(256) void hgemm(
    const __nv_bfloat16* __restrict__ Ahi, const __nv_bfloat16* __restrict__ Alo,
    const __nv_bfloat16* __restrict__ Bhi, const __nv_bfloat16* __restrict__ Blo,
    const float* __restrict__ bias, float* __restrict__ C,
    const float* __restrict__ qin, const float* __restrict__ alpha_ptr, int alpha_idx,
    int Nn, int K)
{
    extern __shared__ __align__(128) char sm[];
    const uint32_t sb = smem_u32(sm);
    const int tid = threadIdx.x;
    const int bm = blockIdx.y * 128, bn = blockIdx.x * 128;
    const int nch = K >> 5;

    // cp.async mapping: thread -> 2 adjacent 16B chunks per tile (512 chunks/tile)
    const int ci   = tid * 2;
    const int crow = ci >> 2;
    const int ccol = (ci & 3) * 16;      // {0, 32}
    const char* pAh = (const char*)Ahi + ((size_t)(bm + crow) * K) * 2 + ccol;
    const char* pAl = (const char*)Alo + ((size_t)(bm + crow) * K) * 2 + ccol;
    const char* pBh = (const char*)Bhi + ((size_t)(bn + crow) * K) * 2 + ccol;
    const char* pBl = (const char*)Blo + ((size_t)(bn + crow) * K) * 2 + ccol;
    const uint32_t dbase = sb + crow * 80 + ccol;

    auto issue = [&](int c) {
        uint32_t db = dbase + (c & (SSN - 1)) * STG_B;
        size_t kb = (size_t)c * 64;      // 32 bf16 * 2B
        CPA(db + 0 * TIL_B,      pAh + kb);
        CPA(db + 0 * TIL_B + 16, pAh + kb + 16);
        CPA(db + 1 * TIL_B,      pAl + kb);
        CPA(db + 1 * TIL_B + 16, pAl + kb + 16);
        CPA(db + 2 * TIL_B,      pBh + kb);
        CPA(db + 2 * TIL_B + 16, pBh + kb + 16);
        CPA(db + 3 * TIL_B,      pBl + kb);
        CPA(db + 3 * TIL_B + 16, pBl + kb + 16);
    };

    // prologue: always commit SSN-1 groups (empty commits keep group math uniform)
    for (int s = 0; s < SSN - 1; s++) {
        if (s < nch) issue(s);
        CP_COMMIT();
    }

    const int lane = tid & 31, w = tid >> 5;
    const int m_off = (w >> 2) * 64;
    const int n_off = (w & 3) * 32;
    // A ldmatrix: lanes 0-15 -> rows, k0; lanes 16-31 -> rows, k0+8
    const uint32_t a_loff = (uint32_t)((m_off + (lane & 15)) * 80 + ((lane >> 4) << 3) * 2);
    // B ldmatrix: groups of 8 lanes -> (n8 half, k8 half)
    const int bg = lane >> 3, bw = lane & 7;
    const uint32_t b_loff = (uint32_t)((n_off + ((bg >> 1) << 3) + bw) * 80 + ((bg & 1) << 3) * 2);

    float acc[4][4][4];
#pragma unroll
    for (int a = 0; a < 4; a++)
#pragma unroll
        for (int b = 0; b < 4; b++)
#pragma unroll
            for (int d = 0; d < 4; d++) acc[a][b][d] = 0.f;

    for (int c = 0; c < nch; c++) {
        __syncthreads();                       // readers of recycled slot done
        if (c + SSN - 1 < nch) issue(c + SSN - 1);
        CP_COMMIT();
        CP_WAIT(SSN - 1);                      // stage c arrived (in-order groups)
        __syncthreads();                       // cross-thread visibility

        uint32_t st = sb + (c & (SSN - 1)) * STG_B;
#pragma unroll
        for (int ks = 0; ks < 2; ks++) {
            uint32_t af[4][4], bh[2][4], bl[2][4];
#pragma unroll
            for (int mi = 0; mi < 4; mi++) ldsm4(af[mi], st + a_loff + mi * 1280 + ks * 32);
#pragma unroll
            for (int p = 0; p < 2; p++) ldsm4(bh[p], st + 2 * TIL_B + b_loff + p * 1280 + ks * 32);
#pragma unroll
            for (int p = 0; p < 2; p++) ldsm4(bl[p], st + 3 * TIL_B + b_loff + p * 1280 + ks * 32);
            // pass 1: Ahi * Bhi
#pragma unroll
            for (int mi = 0; mi < 4; mi++)
#pragma unroll
                for (int ni = 0; ni < 4; ni++)
                    mma16816(acc[mi][ni], af[mi], &bh[ni >> 1][(ni & 1) * 2]);
            // pass 2: Ahi * Blo
#pragma unroll
            for (int mi = 0; mi < 4; mi++)
#pragma unroll
                for (int ni = 0; ni < 4; ni++)
                    mma16816(acc[mi][ni], af[mi], &bl[ni >> 1][(ni & 1) * 2]);
            // pass 3: Alo * Bhi (reuse A frag regs)
#pragma unroll
            for (int mi = 0; mi < 4; mi++) ldsm4(af[mi], st + TIL_B + a_loff + mi * 1280 + ks * 32);
#pragma unroll
            for (int mi = 0; mi < 4; mi++)
#pragma unroll
                for (int ni = 0; ni < 4; ni++)
                    mma16816(acc[mi][ni], af[mi], &bh[ni >> 1][(ni & 1) * 2]);
        }
    }

    // ---------------- epilogue ----------------
    float alpha = (EMODE == 3) ? alpha_ptr[alpha_idx] : 0.f;
#pragma unroll
    for (int mi = 0; mi < 4; mi++) {
#pragma unroll
        for (int ni = 0; ni < 4; ni++) {
            int r0 = bm + m_off + mi * 16 + (lane >> 2);
            int c0 = bn + n_off + ni * 8 + (lane & 3) * 2;
            float b0v = bias[c0], b1v = bias[c0 + 1];
#pragma unroll
            for (int hf = 0; hf < 2; hf++) {
                int r = r0 + hf * 8;
                float vx = acc[mi][ni][hf * 2 + 0] + b0v;
                float vy = acc[mi][ni][hf * 2 + 1] + b1v;
                size_t idx = (size_t)r * Nn + c0;
                if (EMODE == 1) {
                    vx = fmaxf(vx, 0.f); vy = fmaxf(vy, 0.f);
                } else if (EMODE == 3) {
                    float qx = qin[idx], qy = qin[idx + 1];
                    vx = qx - ((vx >= 0.f) ? vx : alpha * vx);
                    vy = qy - ((vy >= 0.f) ? vy : alpha * vy);
                }
                float2 o; o.x = vx; o.y = vy;
                *(float2*)(C + idx) = o;
            }
        }
    }
}

// ---------------- host ----------------
static inline dim3 ggrid(int Nn) { return dim3(Nn / 128, NN / 128); }

extern "C" void kernel_launch(void* const* d_in, const int* in_sizes, int n_in,
                              void* d_out, int out_size)
{
    const float* x      = (const float*)d_in[0];
    const float* W_h0q  = (const float*)d_in[1];
    const float* b_h0q  = (const float*)d_in[2];
    const float* W_sq   = (const float*)d_in[3];
    const float* b_sq   = (const float*)d_in[4];
    const float* W_h0h  = (const float*)d_in[5];
    const float* b_h0h  = (const float*)d_in[6];
    const float* W_S    = (const float*)d_in[7];
    const float* b_S    = (const float*)d_in[8];
    const float* W_q0h  = (const float*)d_in[9];
    const float* b_q0h  = (const float*)d_in[10];
    const float* Wb_Aq  = (const float*)d_in[11];
    const float* bb_Aq  = (const float*)d_in[12];
    const float* Wb_Dh  = (const float*)d_in[13];
    const float* bb_Dh  = (const float*)d_in[14];
    const float* Wb_fh  = (const float*)d_in[15];
    const float* bb_fh  = (const float*)d_in[16];
    const float* Wb_hf  = (const float*)d_in[17];
    const float* bb_hf  = (const float*)d_in[18];
    const float* a_hf   = (const float*)d_in[19];
    const float* Wb_resq= (const float*)d_in[20];
    const float* bb_resq= (const float*)d_in[21];
    const float* W_out  = (const float*)d_in[22];
    const float* b_out  = (const float*)d_in[23];
    float* out = (float*)d_out;

    float *q, *sumq, *sumh, *resS, *resqh, *Aq, *Dh, *h, *bsum;
    cudaGetSymbolAddress((void**)&q,     g_q);
    cudaGetSymbolAddress((void**)&sumq,  g_sumq);
    cudaGetSymbolAddress((void**)&sumh,  g_sumh);
    cudaGetSymbolAddress((void**)&resS,  g_resS);
    cudaGetSymbolAddress((void**)&resqh, g_resqh);
    cudaGetSymbolAddress((void**)&Aq,    g_Aq);
    cudaGetSymbolAddress((void**)&Dh,    g_Dh);
    cudaGetSymbolAddress((void**)&h,     g_h);
    cudaGetSymbolAddress((void**)&bsum,  g_bsum);
    __nv_bfloat16 *whi, *wlo, *ahi, *alo;
    cudaGetSymbolAddress((void**)&whi, g_Whi);
    cudaGetSymbolAddress((void**)&wlo, g_Wlo);
    cudaGetSymbolAddress((void**)&ahi, g_Ahi);
    cudaGetSymbolAddress((void**)&alo, g_Alo);

    cudaFuncSetAttribute(hgemm<0>, cudaFuncAttributeMaxDynamicSharedMemorySize, GSMEM);
    cudaFuncSetAttribute(hgemm<1>, cudaFuncAttributeMaxDynamicSharedMemorySize, GSMEM);
    cudaFuncSetAttribute(hgemm<3>, cudaFuncAttributeMaxDynamicSharedMemorySize, GSMEM);

    // ---- split weights (strided for the SQC concat) ----
#define WS_(src, off, cols, dstride, n) \
    wsplit_k<<<((n) + 255) / 256, 256>>>(src, whi + (off), wlo + (off), cols, dstride, (int)(n))
    WS_(W_sq,   O_SQC,          1024, 1088, (size_t)FF * HH);
    WS_(W_h0q,  O_SQC + 1024,     64, 1088, (size_t)FF * B0K);
    WS_(W_h0h,  O_H0H,            64,   64, (size_t)HH * B0K);
    WS_(W_S,    O_WS,           2048, 2048, (size_t)FF * FF);
    WS_(W_q0h,  O_Q0H,          2048, 2048, (size_t)HH * FF);
    WS_(Wb_Aq,  O_AQ,           2048, 2048, (size_t)NBLK * FF * FF);
    WS_(Wb_Dh,  O_DH,           2048, 2048, (size_t)NBLK * HH * FF);
    WS_(Wb_fh,  O_FH,           2048, 2048, (size_t)NBLK * HH * FF);
    WS_(Wb_hf,  O_HF,           1024, 1024, (size_t)NBLK * FF * HH);
    WS_(Wb_resq,O_RESQ,         2048, 2048, (size_t)NBLK * HH * FF);
    WS_(W_out,  O_OUT,          2048, 2048, (size_t)OO * FF);
#undef WS_
    badd_k<<<FF / 256, 256>>>(b_sq, b_h0q, bsum, FF);

    // q = pi/4 * d^2
    square_k<<<(NN * FF / 4) / 256, 256>>>(x, q);

#define ASPLIT(mode, A0, lda0, A1, A2, A3, K) \
    asplit_k<mode><<<(NN * (K) / 4) / 256, 256>>>(A0, lda0, A1, A2, A3, ahi, alo, (K) / 4, K)

    // sum_q_const = [s|h0] @ SQC^T + (b_sq + b_h0q)      (K = 1088)
    ASPLIT(0, x, XW, nullptr, nullptr, nullptr, 1088);
    hgemm<0><<<ggrid(FF), 256, GSMEM>>>(ahi, alo, whi + O_SQC, wlo + O_SQC,
        bsum, sumq, nullptr, nullptr, 0, FF, 1088);

    // sum_h_const = h0 @ W_h0h^T + b_h0h
    ASPLIT(0, x + HH, XW, nullptr, nullptr, nullptr, B0K);
    hgemm<0><<<ggrid(HH), 256, GSMEM>>>(ahi, alo, whi + O_H0H, wlo + O_H0H,
        b_h0h, sumh, nullptr, nullptr, 0, HH, B0K);

    // res_S_q = relu(d @ W_S^T + b_S)
    ASPLIT(0, x + HH + B0K, XW, nullptr, nullptr, nullptr, FF);
    hgemm<1><<<ggrid(FF), 256, GSMEM>>>(ahi, alo, whi + O_WS, wlo + O_WS,
        b_S, resS, nullptr, nullptr, 0, FF, FF);

    // res_q_h = q @ W_q0h^T + b_q0h
    ASPLIT(0, q, FF, nullptr, nullptr, nullptr, FF);
    hgemm<0><<<ggrid(HH), 256, GSMEM>>>(ahi, alo, whi + O_Q0H, wlo + O_Q0H,
        b_q0h, resqh, nullptr, nullptr, 0, HH, FF);

    for (int i = 0; i < NBLK; i++) {
        const __nv_bfloat16* WAqh = whi + O_AQ   + (size_t)i * FF * FF;
        const __nv_bfloat16* WAql = wlo + O_AQ   + (size_t)i * FF * FF;
        const __nv_bfloat16* WDhh = whi + O_DH   + (size_t)i * HH * FF;
        const __nv_bfloat16* WDhl = wlo + O_DH   + (size_t)i * HH * FF;
        const __nv_bfloat16* Wfhh = whi + O_FH   + (size_t)i * HH * FF;
        const __nv_bfloat16* Wfhl = wlo + O_FH   + (size_t)i * HH * FF;
        const __nv_bfloat16* Whfh = whi + O_HF   + (size_t)i * FF * HH;
        const __nv_bfloat16* Whfl = wlo + O_HF   + (size_t)i * FF * HH;
        const __nv_bfloat16* Wrqh = whi + O_RESQ + (size_t)i * HH * FF;
        const __nv_bfloat16* Wrql = wlo + O_RESQ + (size_t)i * HH * FF;
        const float* b_Aq_i   = bb_Aq   + (size_t)i * FF;
        const float* b_Dh_i   = bb_Dh   + (size_t)i * HH;
        const float* b_fh_i   = bb_fh   + (size_t)i * HH;
        const float* b_hf_i   = bb_hf   + (size_t)i * FF;
        const float* b_resq_i = bb_resq + (size_t)i * HH;

        // A_q = (q * res_S_q) @ W_Aq^T + b_Aq
        ASPLIT(1, q, FF, resS, nullptr, nullptr, FF);
        hgemm<0><<<ggrid(FF), 256, GSMEM>>>(ahi, alo, WAqh, WAql,
            b_Aq_i, Aq, nullptr, nullptr, 0, FF, FF);

        // D_h = relu(A_q @ W_Dh^T + b_Dh)
        ASPLIT(0, Aq, FF, nullptr, nullptr, nullptr, FF);
        hgemm<1><<<ggrid(HH), 256, GSMEM>>>(ahi, alo, WDhh, WDhl,
            b_Dh_i, Dh, nullptr, nullptr, 0, HH, FF);

        // h = relu( (A_q * (q + sum_q_const)) @ W_fh^T + b_fh )
        ASPLIT(2, Aq, FF, q, sumq, nullptr, FF);
        hgemm<1><<<ggrid(HH), 256, GSMEM>>>(ahi, alo, Wfhh, Wfhl,
            b_fh_i, h, nullptr, nullptr, 0, HH, FF);

        // z = leaky(((h + sum_h_const + res_q_h) * D_h) @ W_hf^T + b_hf); q -= z
        ASPLIT(3, h, HH, sumh, resqh, Dh, HH);
        hgemm<3><<<ggrid(FF), 256, GSMEM>>>(ahi, alo, Whfh, Whfl,
            b_hf_i, q, q, a_hf, i, FF, HH);

        // res_q_h = relu(q @ W_resq^T + b_resq)
        ASPLIT(0, q, FF, nullptr, nullptr, nullptr, FF);
        hgemm<1><<<ggrid(HH), 256, GSMEM>>>(ahi, alo, Wrqh, Wrql,
            b_resq_i, resqh, nullptr, nullptr, 0, HH, FF);
    }

    // out = q @ W_out^T + b_out
    ASPLIT(0, q, FF, nullptr, nullptr, nullptr, FF);
    hgemm<0><<<ggrid(OO), 256, GSMEM>>>(ahi, alo, whi + O_OUT, wlo + O_OUT,
        b_out, out, nullptr, nullptr, 0, OO, FF);
#undef ASPLIT
}